// round 3
// baseline (speedup 1.0000x reference)
#include <cuda_runtime.h>
#include <math.h>

#define BDIM 2048
#define HDIM 1024
#define BH (BDIM * HDIM)
#define HH ((size_t)HDIM * HDIM)

// ---------------- scratch pool (static __device__, allocation-free) ----------
// slots (each BH floats):
enum {
    P_XSL  = 0,   // 3: xs@L0..L2
    P_HSR0 = 3,
    P_HSR1 = 4,
    P_Z1   = 5,
    P_R    = 6,
    P_HSL  = 7,   // 3: hs@L0..L2
    P_RR   = 10,  // 3: r@R0..R2
    P_Z1R  = 13,  // 3: z1@R0..R2
    P_RH   = 16,
    P_OMZ  = 17,
    P_Z2H  = 18,
    P_RHR  = 19,  // 3
    P_OMZR = 22,  // 3
    P_HT   = 25,
    P_HTL  = 26,  // 3
    P_ZH   = 29,
    P_ZHL  = 30,  // 3
    P_Z2HR = 33,  // 3
    P_TOTAL = 36
};
__device__ float g_pool[(size_t)P_TOTAL * BH];

// ---------------- batched SGEMM: C = A(2048x1024) @ W(1024x1024) ------------
struct GemmJob { const float* A; const float* W; float* C; };
struct GemmBatch { GemmJob j[9]; };

__global__ void __launch_bounds__(256) sgemm_batch(GemmBatch batch) {
    const GemmJob job = batch.j[blockIdx.z];
    __shared__ float As[16][128];
    __shared__ float Bs[16][128];

    const int tid = threadIdx.x;
    const int m0  = blockIdx.y * 128;
    const int n0  = blockIdx.x * 128;
    const float* A = job.A;
    const float* W = job.W;

    // A-tile load mapping: 512 float4 slots, thread handles tid and tid+256
    const int rowA  = tid >> 2;            // 0..63
    const int rowA2 = rowA + 64;           // 64..127
    const int kqA   = (tid & 3) * 4;       // 0,4,8,12
    // W-tile load mapping
    const int krB  = tid >> 5;             // 0..7
    const int krB2 = krB + 8;              // 8..15
    const int nqB  = (tid & 31) * 4;       // 0..124

    const int rb = (tid >> 4) * 8;         // 0..120
    const int cb = (tid & 15) * 8;         // 0..120

    float acc[8][8];
#pragma unroll
    for (int i = 0; i < 8; i++)
#pragma unroll
        for (int jj = 0; jj < 8; jj++) acc[i][jj] = 0.f;

    for (int kt = 0; kt < HDIM; kt += 16) {
        float4 va = *(const float4*)(A + (size_t)(m0 + rowA)  * HDIM + kt + kqA);
        float4 vb = *(const float4*)(A + (size_t)(m0 + rowA2) * HDIM + kt + kqA);
        float4 wa = *(const float4*)(W + (size_t)(kt + krB)   * HDIM + n0 + nqB);
        float4 wb = *(const float4*)(W + (size_t)(kt + krB2)  * HDIM + n0 + nqB);

        As[kqA + 0][rowA]  = va.x; As[kqA + 1][rowA]  = va.y;
        As[kqA + 2][rowA]  = va.z; As[kqA + 3][rowA]  = va.w;
        As[kqA + 0][rowA2] = vb.x; As[kqA + 1][rowA2] = vb.y;
        As[kqA + 2][rowA2] = vb.z; As[kqA + 3][rowA2] = vb.w;
        *(float4*)&Bs[krB][nqB]  = wa;
        *(float4*)&Bs[krB2][nqB] = wb;
        __syncthreads();

#pragma unroll
        for (int k = 0; k < 16; k++) {
            float4 a0 = *(const float4*)&As[k][rb];
            float4 a1 = *(const float4*)&As[k][rb + 4];
            float4 b0 = *(const float4*)&Bs[k][cb];
            float4 b1 = *(const float4*)&Bs[k][cb + 4];
            float af[8] = {a0.x, a0.y, a0.z, a0.w, a1.x, a1.y, a1.z, a1.w};
            float bf[8] = {b0.x, b0.y, b0.z, b0.w, b1.x, b1.y, b1.z, b1.w};
#pragma unroll
            for (int i = 0; i < 8; i++)
#pragma unroll
                for (int jj = 0; jj < 8; jj++)
                    acc[i][jj] = fmaf(af[i], bf[jj], acc[i][jj]);
        }
        __syncthreads();
    }

    float* C = job.C + (size_t)(m0 + rb) * HDIM + n0 + cb;
#pragma unroll
    for (int i = 0; i < 8; i++) {
        *(float4*)(C + (size_t)i * HDIM)     =
            make_float4(acc[i][0], acc[i][1], acc[i][2], acc[i][3]);
        *(float4*)(C + (size_t)i * HDIM + 4) =
            make_float4(acc[i][4], acc[i][5], acc[i][6], acc[i][7]);
    }
}

// ---------------- fused double sigmoid: z1, r ------------------------------
__global__ void sig_kernel(const float* __restrict__ xsL0, const float* __restrict__ hsR0,
                           const float* __restrict__ xsL1, const float* __restrict__ hsR1,
                           const float* __restrict__ bias,
                           float* __restrict__ z1, float* __restrict__ r) {
    int i = blockIdx.x * blockDim.x + threadIdx.x;
    if (i >= BH) return;
    int h = i & (HDIM - 1);
    float t0 = xsL0[i] + hsR0[i] + bias[h];
    float t1 = xsL1[i] + hsR1[i] + bias[HDIM + h];
    z1[i] = 1.f / (1.f + expf(-t0));
    r[i]  = 1.f / (1.f + expf(-t1));
}

// ---------------- mix kernel: cand -> softmax-mix + argmax -----------------
// cand[k] = op(A3[k], B3[k]) + bias[k]  (k<3);  k==3 uses (a3, b3) (identity lin)
enum { MIX_MUL = 0, MIX_ADD = 1, MIX_ONEMINUS = 2, MIX_TANH = 3 };

template <int OP>
__global__ void __launch_bounds__(256) mix_kernel(
    const float* __restrict__ A3, const float* __restrict__ B3,
    const float* __restrict__ a3, const float* __restrict__ b3,
    const float* __restrict__ bias, const float* __restrict__ w,
    float* __restrict__ out, float* gout, int gcol) {
    const int brow = blockIdx.x;
    const int tid  = threadIdx.x;
    __shared__ float cs[4 * HDIM];
    __shared__ float red[4][8];
    __shared__ float probs[4];

    float part[4] = {0.f, 0.f, 0.f, 0.f};
#pragma unroll
    for (int k = 0; k < 4; k++) {
        const float* pa = (k < 3) ? A3 + (size_t)k * BH + (size_t)brow * HDIM
                                  : a3 + (size_t)brow * HDIM;
        const float* pb = nullptr;
        if (OP != MIX_ONEMINUS)
            pb = (k < 3) ? B3 + (size_t)k * BH + (size_t)brow * HDIM
                         : b3 + (size_t)brow * HDIM;
        for (int h = tid; h < HDIM; h += 256) {
            float bb = bias[k * HDIM + h];
            float c;
            if (OP == MIX_MUL)           c = pa[h] * pb[h] + bb;
            else if (OP == MIX_ADD)      c = pa[h] + pb[h] + bb;
            else if (OP == MIX_ONEMINUS) c = 1.f - (pa[h] + bb);
            else                         c = tanhf(pa[h] + pb[h] + bb);
            cs[k * HDIM + h] = c;
            part[k] += c * w[h];
        }
    }
#pragma unroll
    for (int k = 0; k < 4; k++) {
        float v = part[k];
#pragma unroll
        for (int off = 16; off > 0; off >>= 1)
            v += __shfl_xor_sync(0xffffffffu, v, off);
        if ((tid & 31) == 0) red[k][tid >> 5] = v;
    }
    __syncthreads();
    if (tid == 0) {
        float s[4];
#pragma unroll
        for (int k = 0; k < 4; k++) {
            float t = 0.f;
#pragma unroll
            for (int wq = 0; wq < 8; wq++) t += red[k][wq];
            s[k] = t;
        }
        int g = 0; float mx = s[0];
#pragma unroll
        for (int k = 1; k < 4; k++) if (s[k] > mx) { mx = s[k]; g = k; }
        float e[4], den = 0.f;
#pragma unroll
        for (int k = 0; k < 4; k++) { e[k] = expf(s[k] - mx); den += e[k]; }
#pragma unroll
        for (int k = 0; k < 4; k++) probs[k] = e[k] / den;
        if (gout) gout[(size_t)brow * 9 + gcol] = (float)g;
    }
    __syncthreads();
    float p0 = probs[0], p1 = probs[1], p2 = probs[2], p3 = probs[3];
    for (int h = tid; h < HDIM; h += 256) {
        out[(size_t)brow * HDIM + h] =
            p0 * cs[h] + p1 * cs[HDIM + h] + p2 * cs[2 * HDIM + h] + p3 * cs[3 * HDIM + h];
    }
}

// zero G columns 0..2
__global__ void gzero_kernel(float* G) {
    int i = blockIdx.x * blockDim.x + threadIdx.x;
    if (i < BDIM * 3) G[(size_t)(i / 3) * 9 + (i % 3)] = 0.f;
}

// ---------------- launch orchestration --------------------------------------
extern "C" void kernel_launch(void* const* d_in, const int* in_sizes, int n_in,
                              void* d_out, int out_size) {
    const float* x    = (const float*)d_in[0];  // (B,1,H)
    const float* hp   = (const float*)d_in[1];  // (B,1,H)
    const float* L    = (const float*)d_in[2];  // (4,H,H)
    const float* R    = (const float*)d_in[3];  // (4,H,H)
    const float* bias = (const float*)d_in[4];  // (4,H)
    const float* w    = (const float*)d_in[5];  // (H)
    float* out = (float*)d_out;

    float* pool = nullptr;
    cudaGetSymbolAddress((void**)&pool, g_pool);
    auto P = [&](int idx) { return pool + (size_t)idx * BH; };

    const float* Lk[3] = {L, L + HH, L + 2 * HH};
    const float* Rk[3] = {R, R + HH, R + 2 * HH};

    float* Gf = nullptr;
    if ((size_t)out_size >= (size_t)BH + (size_t)BDIM * 9) Gf = out + BH;

    dim3 tb(256);
    dim3 gg(8, 16, 1);

    // Stage 1: xs@L0, xs@L1, xs@L2, hs@R0, hs@R1  (5 GEMMs)
    {
        GemmBatch bt;
        bt.j[0] = {x,  Lk[0], P(P_XSL + 0)};
        bt.j[1] = {x,  Lk[1], P(P_XSL + 1)};
        bt.j[2] = {x,  Lk[2], P(P_XSL + 2)};
        bt.j[3] = {hp, Rk[0], P(P_HSR0)};
        bt.j[4] = {hp, Rk[1], P(P_HSR1)};
        gg.z = 5;
        sgemm_batch<<<gg, tb>>>(bt);
    }
    // z1 = sigmoid(xsL0 + hsR0 + b0); r = sigmoid(xsL1 + hsR1 + b1); (z2 == z1)
    sig_kernel<<<BH / 256, 256>>>(P(P_XSL + 0), P(P_HSR0), P(P_XSL + 1), P(P_HSR1),
                                  bias, P(P_Z1), P(P_R));

    // Stage 2: hs@Lk, r@Rk, z1@Rk  (9 GEMMs)
    {
        GemmBatch bt;
        for (int k = 0; k < 3; k++) {
            bt.j[k]     = {hp,      Lk[k], P(P_HSL + k)};
            bt.j[3 + k] = {P(P_R),  Rk[k], P(P_RR + k)};
            bt.j[6 + k] = {P(P_Z1), Rk[k], P(P_Z1R + k)};
        }
        gg.z = 9;
        sgemm_batch<<<gg, tb>>>(bt);
    }
    // rh (g3) = mix(hsL * rR + b); omz (g5) = mix(1 - (z1R + b)); z2h (g7) = mix(hsL * z1R + b)
    mix_kernel<MIX_MUL><<<BDIM, 256>>>(P(P_HSL), P(P_RR), hp, P(P_R), bias, w,
                                       P(P_RH), Gf, 3);
    mix_kernel<MIX_ONEMINUS><<<BDIM, 256>>>(P(P_Z1R), nullptr, P(P_Z1), nullptr, bias, w,
                                            P(P_OMZ), Gf, 5);
    mix_kernel<MIX_MUL><<<BDIM, 256>>>(P(P_HSL), P(P_Z1R), hp, P(P_Z1), bias, w,
                                       P(P_Z2H), Gf, 7);

    // Stage 3: rh@Rk, omz@Rk  (6 GEMMs)
    {
        GemmBatch bt;
        for (int k = 0; k < 3; k++) {
            bt.j[k]     = {P(P_RH),  Rk[k], P(P_RHR + k)};
            bt.j[3 + k] = {P(P_OMZ), Rk[k], P(P_OMZR + k)};
        }
        gg.z = 6;
        sgemm_batch<<<gg, tb>>>(bt);
    }
    // h_tilde (g4) = mix(tanh(xsL + rhR + b))
    mix_kernel<MIX_TANH><<<BDIM, 256>>>(P(P_XSL), P(P_RHR), x, P(P_RH), bias, w,
                                        P(P_HT), Gf, 4);

    // Stage 4: h_tilde@Lk  (3 GEMMs)
    {
        GemmBatch bt;
        for (int k = 0; k < 3; k++) bt.j[k] = {P(P_HT), Lk[k], P(P_HTL + k)};
        gg.z = 3;
        sgemm_batch<<<gg, tb>>>(bt);
    }
    // zh_tilde (g6) = mix(htL * omzR + b)
    mix_kernel<MIX_MUL><<<BDIM, 256>>>(P(P_HTL), P(P_OMZR), P(P_HT), P(P_OMZ), bias, w,
                                       P(P_ZH), Gf, 6);

    // Stage 5: zh@Lk, z2h@Rk  (6 GEMMs)
    {
        GemmBatch bt;
        for (int k = 0; k < 3; k++) {
            bt.j[k]     = {P(P_ZH),  Lk[k], P(P_ZHL + k)};
            bt.j[3 + k] = {P(P_Z2H), Rk[k], P(P_Z2HR + k)};
        }
        gg.z = 6;
        sgemm_batch<<<gg, tb>>>(bt);
    }
    // h_next (g8) = mix(zhL + z2hR + b) -> directly into d_out
    mix_kernel<MIX_ADD><<<BDIM, 256>>>(P(P_ZHL), P(P_Z2HR), P(P_ZH), P(P_Z2H), bias, w,
                                       out, Gf, 8);

    if (Gf) gzero_kernel<<<(BDIM * 3 + 255) / 256, 256>>>(Gf);
}

// round 4
// speedup vs baseline: 1.0047x; 1.0047x over previous
#include <cuda_runtime.h>
#include <math.h>

#define BDIM 2048
#define HDIM 1024
#define BH (BDIM * HDIM)
#define HH ((size_t)HDIM * HDIM)

// ---------------- scratch pool (static __device__, allocation-free) ----------
// slots (each BH floats):
enum {
    P_XSL  = 0,   // 3: xs@L0..L2
    P_HSR0 = 3,
    P_HSR1 = 4,
    P_Z1   = 5,
    P_R    = 6,
    P_HSL  = 7,   // 3: hs@L0..L2
    P_RR   = 10,  // 3: r@R0..R2
    P_Z1R  = 13,  // 3: z1@R0..R2
    P_RH   = 16,
    P_OMZ  = 17,
    P_Z2H  = 18,
    P_RHR  = 19,  // 3
    P_OMZR = 22,  // 3
    P_HT   = 25,
    P_HTL  = 26,  // 3
    P_ZH   = 29,
    P_ZHL  = 30,  // 3
    P_Z2HR = 33,  // 3
    P_TOTAL = 36
};
__device__ float g_pool[(size_t)P_TOTAL * BH];

// ---------------- batched SGEMM: C = A(2048x1024) @ W(1024x1024) ------------
struct GemmJob { const float* A; const float* W; float* C; };
struct GemmBatch { GemmJob j[9]; };

__global__ void __launch_bounds__(256) sgemm_batch(GemmBatch batch) {
    const GemmJob job = batch.j[blockIdx.z];
    __shared__ float As[16][128];
    __shared__ float Bs[16][128];

    const int tid = threadIdx.x;
    const int m0  = blockIdx.y * 128;
    const int n0  = blockIdx.x * 128;
    const float* A = job.A;
    const float* W = job.W;

    // A-tile load mapping: 512 float4 slots, thread handles tid and tid+256
    const int rowA  = tid >> 2;            // 0..63
    const int rowA2 = rowA + 64;           // 64..127
    const int kqA   = (tid & 3) * 4;       // 0,4,8,12
    // W-tile load mapping
    const int krB  = tid >> 5;             // 0..7
    const int krB2 = krB + 8;              // 8..15
    const int nqB  = (tid & 31) * 4;       // 0..124

    const int rb = (tid >> 4) * 8;         // 0..120
    const int cb = (tid & 15) * 8;         // 0..120

    float acc[8][8];
#pragma unroll
    for (int i = 0; i < 8; i++)
#pragma unroll
        for (int jj = 0; jj < 8; jj++) acc[i][jj] = 0.f;

    for (int kt = 0; kt < HDIM; kt += 16) {
        float4 va = *(const float4*)(A + (size_t)(m0 + rowA)  * HDIM + kt + kqA);
        float4 vb = *(const float4*)(A + (size_t)(m0 + rowA2) * HDIM + kt + kqA);
        float4 wa = *(const float4*)(W + (size_t)(kt + krB)   * HDIM + n0 + nqB);
        float4 wb = *(const float4*)(W + (size_t)(kt + krB2)  * HDIM + n0 + nqB);

        As[kqA + 0][rowA]  = va.x; As[kqA + 1][rowA]  = va.y;
        As[kqA + 2][rowA]  = va.z; As[kqA + 3][rowA]  = va.w;
        As[kqA + 0][rowA2] = vb.x; As[kqA + 1][rowA2] = vb.y;
        As[kqA + 2][rowA2] = vb.z; As[kqA + 3][rowA2] = vb.w;
        *(float4*)&Bs[krB][nqB]  = wa;
        *(float4*)&Bs[krB2][nqB] = wb;
        __syncthreads();

#pragma unroll
        for (int k = 0; k < 16; k++) {
            float4 a0 = *(const float4*)&As[k][rb];
            float4 a1 = *(const float4*)&As[k][rb + 4];
            float4 b0 = *(const float4*)&Bs[k][cb];
            float4 b1 = *(const float4*)&Bs[k][cb + 4];
            float af[8] = {a0.x, a0.y, a0.z, a0.w, a1.x, a1.y, a1.z, a1.w};
            float bf[8] = {b0.x, b0.y, b0.z, b0.w, b1.x, b1.y, b1.z, b1.w};
#pragma unroll
            for (int i = 0; i < 8; i++)
#pragma unroll
                for (int jj = 0; jj < 8; jj++)
                    acc[i][jj] = fmaf(af[i], bf[jj], acc[i][jj]);
        }
        __syncthreads();
    }

    float* C = job.C + (size_t)(m0 + rb) * HDIM + n0 + cb;
#pragma unroll
    for (int i = 0; i < 8; i++) {
        *(float4*)(C + (size_t)i * HDIM)     =
            make_float4(acc[i][0], acc[i][1], acc[i][2], acc[i][3]);
        *(float4*)(C + (size_t)i * HDIM + 4) =
            make_float4(acc[i][4], acc[i][5], acc[i][6], acc[i][7]);
    }
}

// ---------------- fused double sigmoid: z1, r ------------------------------
__global__ void sig_kernel(const float* __restrict__ xsL0, const float* __restrict__ hsR0,
                           const float* __restrict__ xsL1, const float* __restrict__ hsR1,
                           const float* __restrict__ bias,
                           float* __restrict__ z1, float* __restrict__ r) {
    int i = blockIdx.x * blockDim.x + threadIdx.x;
    if (i >= BH) return;
    int h = i & (HDIM - 1);
    float t0 = xsL0[i] + hsR0[i] + bias[h];
    float t1 = xsL1[i] + hsR1[i] + bias[HDIM + h];
    z1[i] = 1.f / (1.f + expf(-t0));
    r[i]  = 1.f / (1.f + expf(-t1));
}

// ---------------- mix kernel: cand -> softmax-mix + argmax -----------------
// cand[k] = op(A3[k], B3[k]) + bias[k]  (k<3);  k==3 uses (a3, b3) (identity lin)
enum { MIX_MUL = 0, MIX_ADD = 1, MIX_ONEMINUS = 2, MIX_TANH = 3 };

template <int OP>
__global__ void __launch_bounds__(256) mix_kernel(
    const float* __restrict__ A3, const float* __restrict__ B3,
    const float* __restrict__ a3, const float* __restrict__ b3,
    const float* __restrict__ bias, const float* __restrict__ w,
    float* __restrict__ out, float* gout, int gcol) {
    const int brow = blockIdx.x;
    const int tid  = threadIdx.x;
    __shared__ float cs[4 * HDIM];
    __shared__ float red[4][8];
    __shared__ float probs[4];

    float part[4] = {0.f, 0.f, 0.f, 0.f};
#pragma unroll
    for (int k = 0; k < 4; k++) {
        const float* pa = (k < 3) ? A3 + (size_t)k * BH + (size_t)brow * HDIM
                                  : a3 + (size_t)brow * HDIM;
        const float* pb = nullptr;
        if (OP != MIX_ONEMINUS)
            pb = (k < 3) ? B3 + (size_t)k * BH + (size_t)brow * HDIM
                         : b3 + (size_t)brow * HDIM;
        for (int h = tid; h < HDIM; h += 256) {
            float bb = bias[k * HDIM + h];
            float c;
            if (OP == MIX_MUL)           c = pa[h] * pb[h] + bb;
            else if (OP == MIX_ADD)      c = pa[h] + pb[h] + bb;
            else if (OP == MIX_ONEMINUS) c = 1.f - (pa[h] + bb);
            else                         c = tanhf(pa[h] + pb[h] + bb);
            cs[k * HDIM + h] = c;
            part[k] += c * w[h];
        }
    }
#pragma unroll
    for (int k = 0; k < 4; k++) {
        float v = part[k];
#pragma unroll
        for (int off = 16; off > 0; off >>= 1)
            v += __shfl_xor_sync(0xffffffffu, v, off);
        if ((tid & 31) == 0) red[k][tid >> 5] = v;
    }
    __syncthreads();
    if (tid == 0) {
        float s[4];
#pragma unroll
        for (int k = 0; k < 4; k++) {
            float t = 0.f;
#pragma unroll
            for (int wq = 0; wq < 8; wq++) t += red[k][wq];
            s[k] = t;
        }
        int g = 0; float mx = s[0];
#pragma unroll
        for (int k = 1; k < 4; k++) if (s[k] > mx) { mx = s[k]; g = k; }
        float e[4], den = 0.f;
#pragma unroll
        for (int k = 0; k < 4; k++) { e[k] = expf(s[k] - mx); den += e[k]; }
#pragma unroll
        for (int k = 0; k < 4; k++) probs[k] = e[k] / den;
        if (gout) gout[(size_t)brow * 9 + gcol] = (float)g;
    }
    __syncthreads();
    float p0 = probs[0], p1 = probs[1], p2 = probs[2], p3 = probs[3];
    for (int h = tid; h < HDIM; h += 256) {
        out[(size_t)brow * HDIM + h] =
            p0 * cs[h] + p1 * cs[HDIM + h] + p2 * cs[2 * HDIM + h] + p3 * cs[3 * HDIM + h];
    }
}

// zero G columns 0..2
__global__ void gzero_kernel(float* G) {
    int i = blockIdx.x * blockDim.x + threadIdx.x;
    if (i < BDIM * 3) G[(size_t)(i / 3) * 9 + (i % 3)] = 0.f;
}

// ---------------- launch orchestration --------------------------------------
extern "C" void kernel_launch(void* const* d_in, const int* in_sizes, int n_in,
                              void* d_out, int out_size) {
    const float* x    = (const float*)d_in[0];  // (B,1,H)
    const float* hp   = (const float*)d_in[1];  // (B,1,H)
    const float* L    = (const float*)d_in[2];  // (4,H,H)
    const float* R    = (const float*)d_in[3];  // (4,H,H)
    const float* bias = (const float*)d_in[4];  // (4,H)
    const float* w    = (const float*)d_in[5];  // (H)
    float* out = (float*)d_out;

    float* pool = nullptr;
    cudaGetSymbolAddress((void**)&pool, g_pool);
    auto P = [&](int idx) { return pool + (size_t)idx * BH; };

    const float* Lk[3] = {L, L + HH, L + 2 * HH};
    const float* Rk[3] = {R, R + HH, R + 2 * HH};

    float* Gf = nullptr;
    if ((size_t)out_size >= (size_t)BH + (size_t)BDIM * 9) Gf = out + BH;

    dim3 tb(256);
    dim3 gg(8, 16, 1);

    // Stage 1: xs@L0, xs@L1, xs@L2, hs@R0, hs@R1  (5 GEMMs)
    {
        GemmBatch bt;
        bt.j[0] = {x,  Lk[0], P(P_XSL + 0)};
        bt.j[1] = {x,  Lk[1], P(P_XSL + 1)};
        bt.j[2] = {x,  Lk[2], P(P_XSL + 2)};
        bt.j[3] = {hp, Rk[0], P(P_HSR0)};
        bt.j[4] = {hp, Rk[1], P(P_HSR1)};
        gg.z = 5;
        sgemm_batch<<<gg, tb>>>(bt);
    }
    // z1 = sigmoid(xsL0 + hsR0 + b0); r = sigmoid(xsL1 + hsR1 + b1); (z2 == z1)
    sig_kernel<<<BH / 256, 256>>>(P(P_XSL + 0), P(P_HSR0), P(P_XSL + 1), P(P_HSR1),
                                  bias, P(P_Z1), P(P_R));

    // Stage 2: hs@Lk, r@Rk, z1@Rk  (9 GEMMs)
    {
        GemmBatch bt;
        for (int k = 0; k < 3; k++) {
            bt.j[k]     = {hp,      Lk[k], P(P_HSL + k)};
            bt.j[3 + k] = {P(P_R),  Rk[k], P(P_RR + k)};
            bt.j[6 + k] = {P(P_Z1), Rk[k], P(P_Z1R + k)};
        }
        gg.z = 9;
        sgemm_batch<<<gg, tb>>>(bt);
    }
    // rh (g3) = mix(hsL * rR + b); omz (g5) = mix(1 - (z1R + b)); z2h (g7) = mix(hsL * z1R + b)
    mix_kernel<MIX_MUL><<<BDIM, 256>>>(P(P_HSL), P(P_RR), hp, P(P_R), bias, w,
                                       P(P_RH), Gf, 3);
    mix_kernel<MIX_ONEMINUS><<<BDIM, 256>>>(P(P_Z1R), nullptr, P(P_Z1), nullptr, bias, w,
                                            P(P_OMZ), Gf, 5);
    mix_kernel<MIX_MUL><<<BDIM, 256>>>(P(P_HSL), P(P_Z1R), hp, P(P_Z1), bias, w,
                                       P(P_Z2H), Gf, 7);

    // Stage 3: rh@Rk, omz@Rk  (6 GEMMs)
    {
        GemmBatch bt;
        for (int k = 0; k < 3; k++) {
            bt.j[k]     = {P(P_RH),  Rk[k], P(P_RHR + k)};
            bt.j[3 + k] = {P(P_OMZ), Rk[k], P(P_OMZR + k)};
        }
        gg.z = 6;
        sgemm_batch<<<gg, tb>>>(bt);
    }
    // h_tilde (g4) = mix(tanh(xsL + rhR + b))
    mix_kernel<MIX_TANH><<<BDIM, 256>>>(P(P_XSL), P(P_RHR), x, P(P_RH), bias, w,
                                        P(P_HT), Gf, 4);

    // Stage 4: h_tilde@Lk  (3 GEMMs)
    {
        GemmBatch bt;
        for (int k = 0; k < 3; k++) bt.j[k] = {P(P_HT), Lk[k], P(P_HTL + k)};
        gg.z = 3;
        sgemm_batch<<<gg, tb>>>(bt);
    }
    // zh_tilde (g6) = mix(htL * omzR + b)
    mix_kernel<MIX_MUL><<<BDIM, 256>>>(P(P_HTL), P(P_OMZR), P(P_HT), P(P_OMZ), bias, w,
                                       P(P_ZH), Gf, 6);

    // Stage 5: zh@Lk, z2h@Rk  (6 GEMMs)
    {
        GemmBatch bt;
        for (int k = 0; k < 3; k++) {
            bt.j[k]     = {P(P_ZH),  Lk[k], P(P_ZHL + k)};
            bt.j[3 + k] = {P(P_Z2H), Rk[k], P(P_Z2HR + k)};
        }
        gg.z = 6;
        sgemm_batch<<<gg, tb>>>(bt);
    }
    // h_next (g8) = mix(zhL + z2hR + b) -> directly into d_out
    mix_kernel<MIX_ADD><<<BDIM, 256>>>(P(P_ZHL), P(P_Z2HR), P(P_ZH), P(P_Z2H), bias, w,
                                       out, Gf, 8);

    if (Gf) gzero_kernel<<<(BDIM * 3 + 255) / 256, 256>>>(Gf);
}

// round 6
// speedup vs baseline: 2.1613x; 2.1511x over previous
#include <cuda_runtime.h>
#include <cuda_bf16.h>
#include <math.h>
#include <stdint.h>

#define BDIM 2048
#define HDIM 1024
#define BH (BDIM * HDIM)
#define HH ((size_t)HDIM * HDIM)

// ---------------- fp32 scratch pool ----------------------------------------
enum {
    P_XSL  = 0,   // 3
    P_HSR0 = 3,
    P_HSR1 = 4,
    P_Z1   = 5,
    P_R    = 6,
    P_HSL  = 7,   // 3
    P_RR   = 10,  // 3
    P_Z1R  = 13,  // 3
    P_RH   = 16,
    P_OMZ  = 17,
    P_Z2H  = 18,
    P_RHR  = 19,  // 3
    P_OMZR = 22,  // 3
    P_HT   = 25,
    P_HTL  = 26,  // 3
    P_ZH   = 29,
    P_ZHL  = 30,  // 3
    P_Z2HR = 33,  // 3
    P_TOTAL = 36
};
__device__ float g_pool[(size_t)P_TOTAL * BH];

// bf16 hi/lo activation slots (each BH elements)
enum {
    A_XH = 0, A_XL, A_HPH, A_HPL, A_Z1H, A_Z1L, A_RHI, A_RLO,
    A_RHH, A_RHL, A_OMZH, A_OMZL, A_HTH, A_HTL, A_ZHH, A_ZHL,
    A_Z2HH, A_Z2HL, A_TOTAL
};
__device__ __nv_bfloat16 g_act[(size_t)A_TOTAL * BH];

// transposed+split weights: mat m in 0..5 (L0..2, R0..2), hi/lo, layout [N=1024][K=1024]
__device__ __nv_bfloat16 g_wt[(size_t)12 * HH];

// ======================= PTX helpers ========================================
__device__ __forceinline__ uint32_t smem_u32(const void* p) {
    uint32_t a;
    asm("{ .reg .u64 t; cvta.to.shared.u64 t, %1; cvt.u32.u64 %0, t; }"
        : "=r"(a) : "l"(p));
    return a;
}

__device__ __forceinline__ void cpasync16(uint32_t smem, const void* g) {
    asm volatile("cp.async.cg.shared.global [%0], [%1], 16;" :: "r"(smem), "l"(g));
}
#define CP_COMMIT() asm volatile("cp.async.commit_group;" ::: "memory")
#define CP_WAIT1()  asm volatile("cp.async.wait_group 1;" ::: "memory")

__device__ __forceinline__ void ldm_x4(uint32_t* r, uint32_t addr) {
    asm volatile("ldmatrix.sync.aligned.m8n8.x4.shared.b16 {%0,%1,%2,%3}, [%4];"
                 : "=r"(r[0]), "=r"(r[1]), "=r"(r[2]), "=r"(r[3]) : "r"(addr));
}

__device__ __forceinline__ void mma_bf16(float* c, const uint32_t* a,
                                         uint32_t b0, uint32_t b1) {
    asm volatile(
        "mma.sync.aligned.m16n8k16.row.col.f32.bf16.bf16.f32 "
        "{%0,%1,%2,%3}, {%4,%5,%6,%7}, {%8,%9}, {%0,%1,%2,%3};"
        : "+f"(c[0]), "+f"(c[1]), "+f"(c[2]), "+f"(c[3])
        : "r"(a[0]), "r"(a[1]), "r"(a[2]), "r"(a[3]), "r"(b0), "r"(b1));
}

// ======================= mma.sync batched GEMM ===============================
// C(2048x1024,f32) = A(2048x1024) @ Wt^T, A/Wt as bf16 hi/lo pairs,
// Wt stored [N=1024][K=1024] K-major. CTA tile 128x128, kc=32, 2-stage cp.async.
struct Job {
    const __nv_bfloat16* Ah; const __nv_bfloat16* Al;
    const __nv_bfloat16* Bh; const __nv_bfloat16* Bl;
    float* C;
};
struct JobBatch { Job j[9]; };

#define BK      32
#define ROWSTR  80u       // bytes per smem row (40 bf16): conflict-free ldmatrix
#define REGION  10240u    // 128 rows * 80 B
#define STAGEB  40960u    // Ah + Al + Bh + Bl
#define GSMEM   (2 * STAGEB)

__global__ void __launch_bounds__(256, 1) gemm_mma(JobBatch batch) {
    extern __shared__ char dsm[];
    const Job job = batch.j[blockIdx.z];
    const int tid  = threadIdx.x;
    const int lane = tid & 31;
    const int wid  = tid >> 5;
    const int m0 = blockIdx.y * 128, n0 = blockIdx.x * 128;
    const int wm = (wid & 1) * 64;     // warp M offset in tile
    const int wn = (wid >> 1) * 32;    // warp N offset in tile

    const uint32_t sb = smem_u32(dsm);

    const __nv_bfloat16* gp[4] = {job.Ah, job.Al, job.Bh, job.Bl};
    const int row0[4] = {m0, m0, n0, n0};

    // per-thread gmem/smem load mapping: 512 16B-chunks per region, 2 per thread
    const int ldRow0 = tid >> 2, ldCh0 = tid & 3;           // idx = tid
    const int ldRow1 = (tid + 256) >> 2, ldCh1 = tid & 3;   // idx = tid+256

    auto load_stage = [&](int stage, int kt) {
        uint32_t base = sb + (uint32_t)stage * STAGEB;
#pragma unroll
        for (int rgn = 0; rgn < 4; rgn++) {
            uint32_t rb = base + (uint32_t)rgn * REGION;
            const __nv_bfloat16* g = gp[rgn] + (size_t)row0[rgn] * HDIM + kt;
            cpasync16(rb + (uint32_t)ldRow0 * ROWSTR + (uint32_t)ldCh0 * 16u,
                      g + (size_t)ldRow0 * HDIM + ldCh0 * 8);
            cpasync16(rb + (uint32_t)ldRow1 * ROWSTR + (uint32_t)ldCh1 * 16u,
                      g + (size_t)ldRow1 * HDIM + ldCh1 * 8);
        }
    };

    float acc[4][4][4];
#pragma unroll
    for (int i = 0; i < 4; i++)
#pragma unroll
        for (int j = 0; j < 4; j++)
#pragma unroll
            for (int q = 0; q < 4; q++) acc[i][j][q] = 0.f;

    // ldmatrix lane-derived offsets
    const uint32_t aRow = (uint32_t)(wm + (lane & 15));
    const uint32_t aC8  = (uint32_t)((lane >> 4) * 8);         // elems
    const uint32_t bRow = (uint32_t)(wn + ((lane >> 4) & 1) * 8 + (lane & 7));
    const uint32_t bC8  = (uint32_t)(((lane >> 3) & 1) * 8);   // elems

    load_stage(0, 0);
    CP_COMMIT();

#pragma unroll 1
    for (int it = 0; it < 32; ++it) {
        if (it + 1 < 32) load_stage((it + 1) & 1, (it + 1) * BK);
        CP_COMMIT();
        CP_WAIT1();
        __syncthreads();

        const uint32_t base = sb + (uint32_t)(it & 1) * STAGEB;
#pragma unroll
        for (int ks = 0; ks < 2; ks++) {
            uint32_t ah[4][4], al[4][4], bh[2][4], bl[2][4];
#pragma unroll
            for (int mf = 0; mf < 4; mf++) {
                uint32_t ad = base + (aRow + (uint32_t)mf * 16u) * ROWSTR +
                              ((uint32_t)ks * 16u + aC8) * 2u;
                ldm_x4(ah[mf], ad);
                ldm_x4(al[mf], ad + REGION);
            }
#pragma unroll
            for (int p = 0; p < 2; p++) {
                uint32_t bd = base + 2u * REGION +
                              (bRow + (uint32_t)p * 16u) * ROWSTR +
                              ((uint32_t)ks * 16u + bC8) * 2u;
                ldm_x4(bh[p], bd);
                ldm_x4(bl[p], bd + REGION);
            }
            // split-outer ordering: each acc reused every 16 mma (no RAW stall)
#pragma unroll
            for (int mf = 0; mf < 4; mf++)
#pragma unroll
                for (int nf = 0; nf < 4; nf++)
                    mma_bf16(acc[mf][nf], ah[mf],
                             bh[nf >> 1][(nf & 1) * 2], bh[nf >> 1][(nf & 1) * 2 + 1]);
#pragma unroll
            for (int mf = 0; mf < 4; mf++)
#pragma unroll
                for (int nf = 0; nf < 4; nf++)
                    mma_bf16(acc[mf][nf], ah[mf],
                             bl[nf >> 1][(nf & 1) * 2], bl[nf >> 1][(nf & 1) * 2 + 1]);
#pragma unroll
            for (int mf = 0; mf < 4; mf++)
#pragma unroll
                for (int nf = 0; nf < 4; nf++)
                    mma_bf16(acc[mf][nf], al[mf],
                             bh[nf >> 1][(nf & 1) * 2], bh[nf >> 1][(nf & 1) * 2 + 1]);
        }
        __syncthreads();
    }

    // epilogue: direct f32 stores
    float* C = job.C + (size_t)m0 * HDIM + n0;
    const int r4 = lane >> 2, c2 = (lane & 3) * 2;
#pragma unroll
    for (int mf = 0; mf < 4; mf++)
#pragma unroll
        for (int nf = 0; nf < 4; nf++) {
            float* p0 = C + (size_t)(wm + mf * 16 + r4) * HDIM + wn + nf * 8 + c2;
            *(float2*)p0 = make_float2(acc[mf][nf][0], acc[mf][nf][1]);
            *(float2*)(p0 + 8 * HDIM) = make_float2(acc[mf][nf][2], acc[mf][nf][3]);
        }
}

// ---------------- weight transpose + bf16 split -----------------------------
__global__ void wsplit_kernel(const float* __restrict__ L, const float* __restrict__ R,
                              __nv_bfloat16* __restrict__ wt) {
    __shared__ float s[32][33];
    const int m = blockIdx.z;  // 0..5
    const float* W = (m < 3) ? (L + (size_t)m * HH) : (R + (size_t)(m - 3) * HH);
    __nv_bfloat16* dh = wt + (size_t)(2 * m) * HH;
    __nv_bfloat16* dl = wt + (size_t)(2 * m + 1) * HH;
    const int k0 = blockIdx.y * 32, n0 = blockIdx.x * 32;
    const int tx = threadIdx.x, ty = threadIdx.y;
#pragma unroll
    for (int j = 0; j < 32; j += 8)
        s[ty + j][tx] = W[(size_t)(k0 + ty + j) * HDIM + n0 + tx];
    __syncthreads();
#pragma unroll
    for (int j = 0; j < 32; j += 8) {
        float v = s[tx][ty + j];
        __nv_bfloat16 h = __float2bfloat16(v);
        size_t o = (size_t)(n0 + ty + j) * HDIM + k0 + tx;
        dh[o] = h;
        dl[o] = __float2bfloat16(v - __bfloat162float(h));
    }
}

// ---------------- activation bf16 split -------------------------------------
__global__ void asplit_kernel(const float* __restrict__ a,
                              __nv_bfloat16* __restrict__ hi,
                              __nv_bfloat16* __restrict__ lo) {
    int i = blockIdx.x * 256 + threadIdx.x;
    if (i >= BH) return;
    float v = a[i];
    __nv_bfloat16 h = __float2bfloat16(v);
    hi[i] = h;
    lo[i] = __float2bfloat16(v - __bfloat162float(h));
}

// ---------------- fused double sigmoid (+ splits) ---------------------------
__global__ void sig_kernel(const float* __restrict__ xsL0, const float* __restrict__ hsR0,
                           const float* __restrict__ xsL1, const float* __restrict__ hsR1,
                           const float* __restrict__ bias,
                           float* __restrict__ z1, float* __restrict__ r,
                           __nv_bfloat16* __restrict__ z1h, __nv_bfloat16* __restrict__ z1l,
                           __nv_bfloat16* __restrict__ rh, __nv_bfloat16* __restrict__ rl) {
    int i = blockIdx.x * blockDim.x + threadIdx.x;
    if (i >= BH) return;
    int h = i & (HDIM - 1);
    float t0 = xsL0[i] + hsR0[i] + bias[h];
    float t1 = xsL1[i] + hsR1[i] + bias[HDIM + h];
    float v0 = 1.f / (1.f + expf(-t0));
    float v1 = 1.f / (1.f + expf(-t1));
    z1[i] = v0; r[i] = v1;
    __nv_bfloat16 h0 = __float2bfloat16(v0);
    __nv_bfloat16 h1 = __float2bfloat16(v1);
    z1h[i] = h0; z1l[i] = __float2bfloat16(v0 - __bfloat162float(h0));
    rh[i]  = h1; rl[i]  = __float2bfloat16(v1 - __bfloat162float(h1));
}

// ---------------- mix kernel (+ optional bf16 split output) -----------------
enum { MIX_MUL = 0, MIX_ADD = 1, MIX_ONEMINUS = 2, MIX_TANH = 3 };

template <int OP>
__global__ void __launch_bounds__(256) mix_kernel(
    const float* __restrict__ A3, const float* __restrict__ B3,
    const float* __restrict__ a3, const float* __restrict__ b3,
    const float* __restrict__ bias, const float* __restrict__ w,
    float* __restrict__ out,
    __nv_bfloat16* __restrict__ oh, __nv_bfloat16* __restrict__ ol,
    float* gout, int gcol) {
    const int brow = blockIdx.x;
    const int tid  = threadIdx.x;
    __shared__ float cs[4 * HDIM];
    __shared__ float red[4][8];
    __shared__ float probs[4];

    float part[4] = {0.f, 0.f, 0.f, 0.f};
#pragma unroll
    for (int k = 0; k < 4; k++) {
        const float* pa = (k < 3) ? A3 + (size_t)k * BH + (size_t)brow * HDIM
                                  : a3 + (size_t)brow * HDIM;
        const float* pb = nullptr;
        if (OP != MIX_ONEMINUS)
            pb = (k < 3) ? B3 + (size_t)k * BH + (size_t)brow * HDIM
                         : b3 + (size_t)brow * HDIM;
        for (int h = tid; h < HDIM; h += 256) {
            float bb = bias[k * HDIM + h];
            float c;
            if (OP == MIX_MUL)           c = pa[h] * pb[h] + bb;
            else if (OP == MIX_ADD)      c = pa[h] + pb[h] + bb;
            else if (OP == MIX_ONEMINUS) c = 1.f - (pa[h] + bb);
            else                         c = tanhf(pa[h] + pb[h] + bb);
            cs[k * HDIM + h] = c;
            part[k] += c * w[h];
        }
    }
#pragma unroll
    for (int k = 0; k < 4; k++) {
        float v = part[k];
#pragma unroll
        for (int off = 16; off > 0; off >>= 1)
            v += __shfl_xor_sync(0xffffffffu, v, off);
        if ((tid & 31) == 0) red[k][tid >> 5] = v;
    }
    __syncthreads();
    if (tid == 0) {
        float s[4];
#pragma unroll
        for (int k = 0; k < 4; k++) {
            float t = 0.f;
#pragma unroll
            for (int wq = 0; wq < 8; wq++) t += red[k][wq];
            s[k] = t;
        }
        int g = 0; float mx = s[0];
#pragma unroll
        for (int k = 1; k < 4; k++) if (s[k] > mx) { mx = s[k]; g = k; }
        float e[4], den = 0.f;
#pragma unroll
        for (int k = 0; k < 4; k++) { e[k] = expf(s[k] - mx); den += e[k]; }
#pragma unroll
        for (int k = 0; k < 4; k++) probs[k] = e[k] / den;
        if (gout) gout[(size_t)brow * 9 + gcol] = (float)g;
    }
    __syncthreads();
    float p0 = probs[0], p1 = probs[1], p2 = probs[2], p3 = probs[3];
    for (int h = tid; h < HDIM; h += 256) {
        float v = p0 * cs[h] + p1 * cs[HDIM + h] + p2 * cs[2 * HDIM + h] +
                  p3 * cs[3 * HDIM + h];
        size_t idx = (size_t)brow * HDIM + h;
        out[idx] = v;
        if (oh) {
            __nv_bfloat16 hh = __float2bfloat16(v);
            oh[idx] = hh;
            ol[idx] = __float2bfloat16(v - __bfloat162float(hh));
        }
    }
}

__global__ void gzero_kernel(float* G) {
    int i = blockIdx.x * blockDim.x + threadIdx.x;
    if (i < BDIM * 3) G[(size_t)(i / 3) * 9 + (i % 3)] = 0.f;
}

// ---------------- orchestration ---------------------------------------------
extern "C" void kernel_launch(void* const* d_in, const int* in_sizes, int n_in,
                              void* d_out, int out_size) {
    const float* x    = (const float*)d_in[0];
    const float* hp   = (const float*)d_in[1];
    const float* L    = (const float*)d_in[2];
    const float* R    = (const float*)d_in[3];
    const float* bias = (const float*)d_in[4];
    const float* w    = (const float*)d_in[5];
    float* out = (float*)d_out;

    float* pool = nullptr;
    __nv_bfloat16* act = nullptr;
    __nv_bfloat16* wt  = nullptr;
    cudaGetSymbolAddress((void**)&pool, g_pool);
    cudaGetSymbolAddress((void**)&act,  g_act);
    cudaGetSymbolAddress((void**)&wt,   g_wt);
    auto P  = [&](int idx) { return pool + (size_t)idx * BH; };
    auto AB = [&](int idx) { return act + (size_t)idx * BH; };
    auto WT = [&](int m, int hl) { return wt + (size_t)(2 * m + hl) * HH; };
    // mats: 0..2 = L0..2, 3..5 = R0..2

    cudaFuncSetAttribute(gemm_mma, cudaFuncAttributeMaxDynamicSharedMemorySize, GSMEM);

    float* Gf = nullptr;
    if ((size_t)out_size >= (size_t)BH + (size_t)BDIM * 9) Gf = out + BH;

    // preprocessing: weight transpose+split, activation splits
    wsplit_kernel<<<dim3(32, 32, 6), dim3(32, 8)>>>(L, R, wt);
    asplit_kernel<<<BH / 256, 256>>>(x,  AB(A_XH),  AB(A_XL));
    asplit_kernel<<<BH / 256, 256>>>(hp, AB(A_HPH), AB(A_HPL));

    dim3 gg(8, 16, 1);

    // Stage 1: xs@L0..2, hs@R0, hs@R1
    {
        JobBatch bt;
        for (int k = 0; k < 3; k++)
            bt.j[k] = {AB(A_XH), AB(A_XL), WT(k, 0), WT(k, 1), P(P_XSL + k)};
        bt.j[3] = {AB(A_HPH), AB(A_HPL), WT(3, 0), WT(3, 1), P(P_HSR0)};
        bt.j[4] = {AB(A_HPH), AB(A_HPL), WT(4, 0), WT(4, 1), P(P_HSR1)};
        gg.z = 5;
        gemm_mma<<<gg, 256, GSMEM>>>(bt);
    }
    sig_kernel<<<BH / 256, 256>>>(P(P_XSL + 0), P(P_HSR0), P(P_XSL + 1), P(P_HSR1),
                                  bias, P(P_Z1), P(P_R),
                                  AB(A_Z1H), AB(A_Z1L), AB(A_RHI), AB(A_RLO));

    // Stage 2: hs@Lk, r@Rk, z1@Rk
    {
        JobBatch bt;
        for (int k = 0; k < 3; k++) {
            bt.j[k]     = {AB(A_HPH), AB(A_HPL), WT(k, 0),     WT(k, 1),     P(P_HSL + k)};
            bt.j[3 + k] = {AB(A_RHI), AB(A_RLO), WT(3 + k, 0), WT(3 + k, 1), P(P_RR + k)};
            bt.j[6 + k] = {AB(A_Z1H), AB(A_Z1L), WT(3 + k, 0), WT(3 + k, 1), P(P_Z1R + k)};
        }
        gg.z = 9;
        gemm_mma<<<gg, 256, GSMEM>>>(bt);
    }
    mix_kernel<MIX_MUL><<<BDIM, 256>>>(P(P_HSL), P(P_RR), hp, P(P_R), bias, w,
                                       P(P_RH), AB(A_RHH), AB(A_RHL), Gf, 3);
    mix_kernel<MIX_ONEMINUS><<<BDIM, 256>>>(P(P_Z1R), nullptr, P(P_Z1), nullptr, bias, w,
                                            P(P_OMZ), AB(A_OMZH), AB(A_OMZL), Gf, 5);
    mix_kernel<MIX_MUL><<<BDIM, 256>>>(P(P_HSL), P(P_Z1R), hp, P(P_Z1), bias, w,
                                       P(P_Z2H), AB(A_Z2HH), AB(A_Z2HL), Gf, 7);

    // Stage 3: rh@Rk, omz@Rk
    {
        JobBatch bt;
        for (int k = 0; k < 3; k++) {
            bt.j[k]     = {AB(A_RHH),  AB(A_RHL),  WT(3 + k, 0), WT(3 + k, 1), P(P_RHR + k)};
            bt.j[3 + k] = {AB(A_OMZH), AB(A_OMZL), WT(3 + k, 0), WT(3 + k, 1), P(P_OMZR + k)};
        }
        gg.z = 6;
        gemm_mma<<<gg, 256, GSMEM>>>(bt);
    }
    mix_kernel<MIX_TANH><<<BDIM, 256>>>(P(P_XSL), P(P_RHR), x, P(P_RH), bias, w,
                                        P(P_HT), AB(A_HTH), AB(A_HTL), Gf, 4);

    // Stage 4: ht@Lk
    {
        JobBatch bt;
        for (int k = 0; k < 3; k++)
            bt.j[k] = {AB(A_HTH), AB(A_HTL), WT(k, 0), WT(k, 1), P(P_HTL + k)};
        gg.z = 3;
        gemm_mma<<<gg, 256, GSMEM>>>(bt);
    }
    mix_kernel<MIX_MUL><<<BDIM, 256>>>(P(P_HTL), P(P_OMZR), P(P_HT), P(P_OMZ), bias, w,
                                       P(P_ZH), AB(A_ZHH), AB(A_ZHL), Gf, 6);

    // Stage 5: zh@Lk, z2h@Rk
    {
        JobBatch bt;
        for (int k = 0; k < 3; k++) {
            bt.j[k]     = {AB(A_ZHH),  AB(A_ZHL),  WT(k, 0),     WT(k, 1),     P(P_ZHL + k)};
            bt.j[3 + k] = {AB(A_Z2HH), AB(A_Z2HL), WT(3 + k, 0), WT(3 + k, 1), P(P_Z2HR + k)};
        }
        gg.z = 6;
        gemm_mma<<<gg, 256, GSMEM>>>(bt);
    }
    mix_kernel<MIX_ADD><<<BDIM, 256>>>(P(P_ZHL), P(P_Z2HR), P(P_ZH), P(P_Z2H), bias, w,
                                       out, nullptr, nullptr, Gf, 8);

    if (Gf) gzero_kernel<<<(BDIM * 3 + 255) / 256, 256>>>(Gf);
}